// round 17
// baseline (speedup 1.0000x reference)
#include <cuda_runtime.h>
#include <cuda_fp16.h>
#include <cstdint>

#define C 64
#define MAXN 50000
#define MAXE 800000

// ---------------- device scratch (static: no allocation allowed) ----------------
__device__ float  g_v[MAXN * C];
__device__ __half g_hQ1[MAXN * C];
__device__ __half g_hK1[MAXN * C];
__device__ float4 g_pos4[MAXN];
__device__ float  g_num[MAXN * C];
__device__ float  g_den[MAXN * C];
__device__ float g_Mq_t[C * C];
__device__ float g_Mk_t[C * C];
__device__ float g_Win_t[C * C];
__device__ float g_Wlin_t[C * C];
__device__ float g_w2a_t[C * C];
__device__ float g_w2p_t[C * C];
__device__ float g_Wout_t[C * C];
__device__ float g_delta0[C];
// fp16 B fragments (m16n8k16): [(kt*8+nt)*32+lane] -> uint2 {b0,b1}
__device__ uint2 g_hWin[1024];
__device__ uint2 g_hWlin[1024];
__device__ uint2 g_hMq[1024];
__device__ uint2 g_hMk[1024];
__device__ uint2 g_hW2a[1024];
__device__ uint2 g_hW2p[1024];
__device__ uint2 g_hWout[1024];

__device__ __forceinline__ unsigned pack_h2(float a, float b) {
    __half2 h = __floats2half2_rn(a, b);
    return *reinterpret_cast<unsigned*>(&h);
}

#define MMA_F16(d, a, b0, b1)                                                \
    asm volatile("mma.sync.aligned.m16n8k16.row.col.f32.f16.f16.f32 "        \
                 "{%0,%1,%2,%3}, {%4,%5,%6,%7}, {%8,%9}, {%0,%1,%2,%3};"     \
                 : "+f"(d[0]), "+f"(d[1]), "+f"(d[2]), "+f"(d[3])            \
                 : "r"(a[0]), "r"(a[1]), "r"(a[2]), "r"(a[3]),               \
                   "r"(b0), "r"(b1))

#define RED_V4(ptr, v)                                                       \
    asm volatile("red.global.add.v4.f32 [%0], {%1,%2,%3,%4};"                \
                 :: "l"(ptr), "f"((v).x), "f"((v).y), "f"((v).z), "f"((v).w) \
                 : "memory")

#define HBAR(id)                                                             \
    asm volatile("bar.sync %0, 128;" :: "r"(id) : "memory")

__device__ __forceinline__ void ldsm_x4(unsigned& r0, unsigned& r1,
                                        unsigned& r2, unsigned& r3, unsigned addr) {
    asm volatile("ldmatrix.sync.aligned.m8n8.x4.shared.b16 {%0,%1,%2,%3}, [%4];"
                 : "=r"(r0), "=r"(r1), "=r"(r2), "=r"(r3) : "r"(addr));
}

__device__ __forceinline__ uint32_t smem_u32(const void* p) {
    uint32_t r;
    asm("{ .reg .u64 t; cvta.to.shared.u64 t, %1; cvt.u32.u64 %0, t; }"
        : "=r"(r) : "l"(p));
    return r;
}

// ---------------- K0: weight prep ------------------------------------------------
__global__ void prep_kernel(const float* __restrict__ att_w1,
                            const float* __restrict__ W_dst,
                            const float* __restrict__ W_src,
                            const float* __restrict__ W_in,
                            const float* __restrict__ W_lin,
                            const float* __restrict__ att_w2,
                            const float* __restrict__ pos_w2,
                            const float* __restrict__ W_out,
                            const float* __restrict__ pos_b1,
                            const float* __restrict__ pos_b2)
{
    __shared__ float s_a[C * C];
    __shared__ float s_d[C * C];
    __shared__ float s_s[C * C];
    int tid = threadIdx.x;
    for (int t = tid; t < C * C; t += blockDim.x) {
        s_a[t] = att_w1[t];
        s_d[t] = W_dst[t];
        s_s[t] = W_src[t];
    }
    __syncthreads();
    for (int idx = tid; idx < C * C; idx += blockDim.x) {
        int t = idx >> 6, j = idx & 63;
        float aq = 0.f, ak = 0.f;
        #pragma unroll 8
        for (int u = 0; u < C; u++) {
            float a = s_a[t * C + u];
            aq = fmaf(a, s_d[u * C + j], aq);
            ak = fmaf(a, s_s[u * C + j], ak);
        }
        g_Mq_t[j * C + t] = aq;
        g_Mk_t[j * C + t] = ak;
    }
    for (int idx = tid; idx < C * C; idx += blockDim.x) {
        int cc = idx >> 6, j = idx & 63;
        g_Win_t[j * C + cc]  = W_in[idx];
        g_Wlin_t[j * C + cc] = W_lin[idx];
        g_w2a_t[j * C + cc]  = att_w2[idx];
        g_w2p_t[j * C + cc]  = pos_w2[idx];
        g_Wout_t[j * C + cc] = W_out[idx];
    }
    if (tid < C) {
        float acc = pos_b2[tid];
        #pragma unroll 8
        for (int j = 0; j < C; j++)
            acc = fmaf(fmaxf(pos_b1[j], 0.f), pos_w2[tid * C + j], acc);
        g_delta0[tid] = fmaxf(acc, 0.f);
    }
    __syncthreads();
    for (int t = tid; t < 1024; t += blockDim.x) {
        int kt   = t >> 8;
        int nt   = (t >> 5) & 7;
        int lane = t & 31;
        int tig = lane & 3, gid = lane >> 2;
        int n  = nt * 8 + gid;
        int k0 = kt * 16 + tig * 2;
        #define BUILD(dst, srcm)                                             \
            { uint2 u;                                                        \
              u.x = pack_h2(srcm[k0 * 64 + n],       srcm[(k0 + 1) * 64 + n]);\
              u.y = pack_h2(srcm[(k0 + 8) * 64 + n], srcm[(k0 + 9) * 64 + n]);\
              dst[t] = u; }
        BUILD(g_hWin,  g_Win_t)
        BUILD(g_hWlin, g_Wlin_t)
        BUILD(g_hMq,   g_Mq_t)
        BUILD(g_hMk,   g_Mk_t)
        BUILD(g_hW2a,  g_w2a_t)
        BUILD(g_hW2p,  g_w2p_t)
        BUILD(g_hWout, g_Wout_t)
        #undef BUILD
    }
}

// ---------------- K1: node kernel — fp16 MMA + coalesced staged stores ----------
// smem: xs half[64*72] @0, hs half[64*72] @9216,
//       fbufA float[64*68] @18432, fbufB float[64*68] @35840   (total 53248)
__global__ void __launch_bounds__(256)
node_kernel(const float* __restrict__ x,
            const float* __restrict__ pos,
            const float* __restrict__ b_in,
            const float* __restrict__ att_b1,
            const float* __restrict__ att_b2,
            int n)
{
    extern __shared__ char smN[];
    __half* xs    = (__half*)smN;
    __half* hs    = (__half*)(smN + 9216);
    float*  fbufA = (float*)(smN + 18432);
    float*  fbufB = (float*)(smN + 35840);
    __half* fbKh  = (__half*)fbufB;          // half view (pitch 72) for K staging
    int tid  = threadIdx.x;
    int lane = tid & 31;
    int wid  = tid >> 5;
    int base = blockIdx.x * 64;

    // ---- P0: load x -> xs, pos -> g_pos4 ----
    for (int t = tid; t < 1024; t += 256) {
        int row = t >> 4;
        int col = (t & 15) * 4;
        int node = base + row;
        float4 v4 = make_float4(0.f, 0.f, 0.f, 0.f);
        if (node < n) v4 = *(const float4*)(x + (size_t)node * C + col);
        uint2 u;
        u.x = pack_h2(v4.x, v4.y);
        u.y = pack_h2(v4.z, v4.w);
        *(uint2*)(xs + row * 72 + col) = u;
    }
    if (tid < 64) {
        int node = base + tid;
        if (node < n) {
            g_pos4[node] = make_float4(pos[(size_t)node * 3 + 0],
                                       pos[(size_t)node * 3 + 1],
                                       pos[(size_t)node * 3 + 2], 0.f);
        }
    }
    __syncthreads();

    int r0 = (wid & 3) * 16;
    int nh = wid >> 2;
    int n0 = nh * 32;
    int rA = lane >> 2;
    int cb = 2 * (lane & 3);

    uint32_t aX = smem_u32(xs) + (uint32_t)(((r0 + (lane & 15)) * 72 + ((lane >> 4) << 3)) * 2);
    uint32_t aH = smem_u32(hs) + (uint32_t)(((r0 + (lane & 15)) * 72 + ((lane >> 4) << 3)) * 2);

    // ---- P1: GEMM1: h = relu(x @ Win^T + b_in) -> hs ----
    {
        float acc[4][4];
        #pragma unroll
        for (int nt = 0; nt < 4; nt++) {
            int col = n0 + nt * 8 + cb;
            float b0 = b_in[col], b1 = b_in[col + 1];
            acc[nt][0] = b0; acc[nt][1] = b1; acc[nt][2] = b0; acc[nt][3] = b1;
        }
        #pragma unroll
        for (int kt = 0; kt < 4; kt++) {
            unsigned a[4];
            ldsm_x4(a[0], a[1], a[2], a[3], aX + kt * 32);
            #pragma unroll
            for (int nt = 0; nt < 4; nt++) {
                uint2 b = g_hWin[(kt * 8 + nh * 4 + nt) * 32 + lane];
                MMA_F16(acc[nt], a, b.x, b.y);
            }
        }
        #pragma unroll
        for (int nt = 0; nt < 4; nt++) {
            int col = n0 + nt * 8 + cb;
            *(unsigned*)(hs + (r0 + rA) * 72 + col) =
                pack_h2(fmaxf(acc[nt][0], 0.f), fmaxf(acc[nt][1], 0.f));
            *(unsigned*)(hs + (r0 + 8 + rA) * 72 + col) =
                pack_h2(fmaxf(acc[nt][2], 0.f), fmaxf(acc[nt][3], 0.f));
        }
    }
    __syncthreads();

    // ---- P2: GEMM2 fused: v/q/k; av kept in regs; av->fbufA, act->xs ----
    float av[4][4], aq[4][4], ak[4][4];
    {
        #pragma unroll
        for (int nt = 0; nt < 4; nt++)
            #pragma unroll
            for (int q = 0; q < 4; q++) { av[nt][q] = 0.f; aq[nt][q] = 0.f; ak[nt][q] = 0.f; }
        #pragma unroll
        for (int kt = 0; kt < 4; kt++) {
            unsigned a[4];
            ldsm_x4(a[0], a[1], a[2], a[3], aH + kt * 32);
            #pragma unroll
            for (int nt = 0; nt < 4; nt++) {
                int fi = (kt * 8 + nh * 4 + nt) * 32 + lane;
                uint2 bv = g_hWlin[fi];
                uint2 bq = g_hMq[fi];
                uint2 bk = g_hMk[fi];
                MMA_F16(av[nt], a, bv.x, bv.y);
                MMA_F16(aq[nt], a, bq.x, bq.y);
                MMA_F16(ak[nt], a, bk.x, bk.y);
            }
        }
        #pragma unroll
        for (int nt = 0; nt < 4; nt++) {
            int col = n0 + nt * 8 + cb;
            fbufA[(r0 + rA) * 68 + col]         = av[nt][0];
            fbufA[(r0 + rA) * 68 + col + 1]     = av[nt][1];
            fbufA[(r0 + 8 + rA) * 68 + col]     = av[nt][2];
            fbufA[(r0 + 8 + rA) * 68 + col + 1] = av[nt][3];
            float ba0 = att_b1[col], ba1 = att_b1[col + 1];
            *(unsigned*)(xs + (r0 + rA) * 72 + col) =
                pack_h2(fmaxf(aq[nt][0] - ak[nt][0] + ba0, 0.f),
                        fmaxf(aq[nt][1] - ak[nt][1] + ba1, 0.f));
            *(unsigned*)(xs + (r0 + 8 + rA) * 72 + col) =
                pack_h2(fmaxf(aq[nt][2] - ak[nt][2] + ba0, 0.f),
                        fmaxf(aq[nt][3] - ak[nt][3] + ba1, 0.f));
        }
    }
    __syncthreads();

    // ---- P3: coalesced v store (fbufA); stage Q->hs, K->fbKh ----
    #pragma unroll
    for (int p = 0; p < 4; p++) {
        int row = (tid >> 4) + p * 16;
        int node = base + row;
        int col = (tid & 15) * 4;
        if (node < n)
            *(float4*)(g_v + (size_t)node * C + col) = *(const float4*)(fbufA + row * 68 + col);
    }
    #pragma unroll
    for (int nt = 0; nt < 4; nt++) {
        int col = n0 + nt * 8 + cb;
        *(unsigned*)(hs + (r0 + rA) * 72 + col)      = pack_h2(aq[nt][0], aq[nt][1]);
        *(unsigned*)(hs + (r0 + 8 + rA) * 72 + col)  = pack_h2(aq[nt][2], aq[nt][3]);
        *(unsigned*)(fbKh + (r0 + rA) * 72 + col)     = pack_h2(ak[nt][0], ak[nt][1]);
        *(unsigned*)(fbKh + (r0 + 8 + rA) * 72 + col) = pack_h2(ak[nt][2], ak[nt][3]);
    }
    __syncthreads();

    // ---- P4: coalesced Q/K stores + GEMM3 compute ----
    #pragma unroll
    for (int p = 0; p < 2; p++) {
        int row = (tid >> 3) + p * 32;
        int node = base + row;
        int colh = (tid & 7) * 8;
        if (node < n) {
            *(uint4*)(g_hQ1 + (size_t)node * C + colh) = *(const uint4*)(hs + row * 72 + colh);
            *(uint4*)(g_hK1 + (size_t)node * C + colh) = *(const uint4*)(fbKh + row * 72 + colh);
        }
    }
    float acc3[4][4];
    {
        #pragma unroll
        for (int nt = 0; nt < 4; nt++) {
            int col = n0 + nt * 8 + cb;
            float b0 = att_b2[col], b1 = att_b2[col + 1];
            acc3[nt][0] = b0; acc3[nt][1] = b1; acc3[nt][2] = b0; acc3[nt][3] = b1;
        }
        #pragma unroll
        for (int kt = 0; kt < 4; kt++) {
            unsigned a[4];
            ldsm_x4(a[0], a[1], a[2], a[3], aX + kt * 32);
            #pragma unroll
            for (int nt = 0; nt < 4; nt++) {
                uint2 b = g_hW2a[(kt * 8 + nh * 4 + nt) * 32 + lane];
                MMA_F16(acc3[nt], a, b.x, b.y);
            }
        }
    }
    __syncthreads();

    // ---- P5: stage num->fbufA, den->fbufB ----
    #pragma unroll
    for (int nt = 0; nt < 4; nt++) {
        int col = n0 + nt * 8 + cb;
        float d0 = g_delta0[col], d1 = g_delta0[col + 1];
        float e0 = __expf(fmaxf(acc3[nt][0], 0.f));
        float e1 = __expf(fmaxf(acc3[nt][1], 0.f));
        float e2 = __expf(fmaxf(acc3[nt][2], 0.f));
        float e3 = __expf(fmaxf(acc3[nt][3], 0.f));
        fbufB[(r0 + rA) * 68 + col]         = e0;
        fbufB[(r0 + rA) * 68 + col + 1]     = e1;
        fbufB[(r0 + 8 + rA) * 68 + col]     = e2;
        fbufB[(r0 + 8 + rA) * 68 + col + 1] = e3;
        fbufA[(r0 + rA) * 68 + col]         = e0 * (av[nt][0] + d0);
        fbufA[(r0 + rA) * 68 + col + 1]     = e1 * (av[nt][1] + d1);
        fbufA[(r0 + 8 + rA) * 68 + col]     = e2 * (av[nt][2] + d0);
        fbufA[(r0 + 8 + rA) * 68 + col + 1] = e3 * (av[nt][3] + d1);
    }
    __syncthreads();

    // ---- P6: coalesced num/den stores ----
    #pragma unroll
    for (int p = 0; p < 4; p++) {
        int row = (tid >> 4) + p * 16;
        int node = base + row;
        int col = (tid & 15) * 4;
        if (node < n) {
            *(float4*)(g_num + (size_t)node * C + col) = *(const float4*)(fbufA + row * 68 + col);
            *(float4*)(g_den + (size_t)node * C + col) = *(const float4*)(fbufB + row * 68 + col);
        }
    }
}

// ---------------- K2: edge kernel — R13 champion (half-pipelines) ---------------
__global__ void __launch_bounds__(256, 3)
edge_kernel(const int* __restrict__ src, const int* __restrict__ dst,
            const float* __restrict__ att_b1, const float* __restrict__ pos_b1,
            const float* __restrict__ pos_w1,
            const float* __restrict__ att_b2, const float* __restrict__ pos_b2,
            int E)
{
    extern __shared__ char smE[];
    int tid  = threadIdx.x;
    int lane = tid & 31;
    int wid  = tid >> 5;
    bool isA = (wid < 4);
    int sub  = wid & 3;
    int h    = sub >> 1;
    int nhE  = sub & 1;
    int n0b  = nhE * 32;

    char* hb = smE + h * 27136;
    __half* hidA16 = (__half*)hb;
    __half* hidP16 = (__half*)(hb + 4608);
    float*  exA    = (float*)(hb + 9216);
    float*  dlP    = (float*)(hb + 17920);
    int*    seB    = (int*)(hb + 26624);
    int*    deB    = (int*)(hb + 26880);

    const float* b2 = isA ? att_b2 : pos_b2;
    __half* hid = isA ? hidA16 : hidP16;
    float*  res = isA ? exA    : dlP;

    uint2 bB[4][4];
    {
        const uint2* hw2 = isA ? g_hW2a : g_hW2p;
        #pragma unroll
        for (int kt = 0; kt < 4; kt++)
            #pragma unroll
            for (int nt = 0; nt < 4; nt++)
                bB[kt][nt] = hw2[((kt * 8) + nhE * 4 + nt) * 32 + lane];
    }
    float bias0[4], bias1[4];
    #pragma unroll
    for (int nt = 0; nt < 4; nt++) {
        int col = n0b + nt * 8 + 2 * (lane & 3);
        bias0[nt] = b2[col];
        bias1[nt] = b2[col + 1];
    }

    int hwi  = (wid & 1) | ((wid >> 2) << 1);
    int htid = hwi * 32 + lane;
    int hgrp = htid >> 4;
    int js   = (htid & 15) << 2;

    float4 ba1 = *(const float4*)(att_b1 + js);
    __half2 ba1h0 = __floats2half2_rn(ba1.x, ba1.y);
    __half2 ba1h1 = __floats2half2_rn(ba1.z, ba1.w);
    __half2 hzero = __floats2half2_rn(0.f, 0.f);
    float4 bp1 = *(const float4*)(pos_b1 + js);
    float4 pwx, pwy, pwz;
    {
        float3 w0 = *(const float3*)(pos_w1 + (js + 0) * 3);
        float3 w1 = *(const float3*)(pos_w1 + (js + 1) * 3);
        float3 w2 = *(const float3*)(pos_w1 + (js + 2) * 3);
        float3 w3 = *(const float3*)(pos_w1 + (js + 3) * 3);
        pwx = make_float4(w0.x, w1.x, w2.x, w3.x);
        pwy = make_float4(w0.y, w1.y, w2.y, w3.y);
        pwz = make_float4(w0.z, w1.z, w2.z, w3.z);
    }

    uint32_t hidBase = smem_u32(hid);
    uint32_t aAddr0 = hidBase + (uint32_t)((((lane & 15)) * 72 + ((lane >> 4) << 3)) * 2);
    uint32_t aAddr1 = hidBase + (uint32_t)(((16 + (lane & 15)) * 72 + ((lane >> 4) << 3)) * 2);

    int sPrev[4], dPrev[4];
    #pragma unroll
    for (int k = 0; k < 4; k++) dPrev[k] = -1;

    int nvt    = (E + 31) >> 5;
    int H      = blockIdx.x * 2 + h;
    int stride = gridDim.x * 2;
    int barId  = h + 1;

    if (H < nvt) {
        if (htid < 32) {
            int e = (H << 5) + htid;
            seB[htid] = (e < E) ? src[e] : 0;
        } else if (htid < 64) {
            int e = (H << 5) + htid - 32;
            deB[htid - 32] = (e < E) ? dst[e] : -1;
        }
    }
    __syncthreads();

    int it = 0;
    for (int vt = H; vt < nvt; vt += stride, it ^= 1) {
        #pragma unroll
        for (int k = 0; k < 4; k++) {
            int d = dPrev[k];
            if (d >= 0) {
                int e = hgrp + 8 * k;
                float4 ex = *(const float4*)(exA + e * 68 + js);
                float4 dl = *(const float4*)(dlP + e * 68 + js);
                float4 vv = *(const float4*)(g_v + (size_t)sPrev[k] * C + js);
                float4 nv;
                nv.x = ex.x * (vv.x + dl.x);
                nv.y = ex.y * (vv.y + dl.y);
                nv.z = ex.z * (vv.z + dl.z);
                nv.w = ex.w * (vv.w + dl.w);
                RED_V4(g_num + (size_t)d * C + js, nv);
                RED_V4(g_den + (size_t)d * C + js, ex);
            }
        }
        #pragma unroll
        for (int k = 0; k < 4; k++) {
            int e = hgrp + 8 * k;
            int s = seB[it * 32 + e];
            int d = deB[it * 32 + e];
            sPrev[k] = s;
            dPrev[k] = d;
            int dc = d < 0 ? 0 : d;
            uint2 qu = *(const uint2*)(g_hQ1 + (size_t)dc * C + js);
            uint2 ku = *(const uint2*)(g_hK1 + (size_t)s  * C + js);
            float4 p4d = g_pos4[dc];
            float4 p4s = g_pos4[s];
            float dpx = p4d.x - p4s.x, dpy = p4d.y - p4s.y, dpz = p4d.z - p4s.z;
            uint2 ua, up;
            if (d >= 0) {
                __half2 q0 = *(__half2*)&qu.x, q1 = *(__half2*)&qu.y;
                __half2 k0 = *(__half2*)&ku.x, k1 = *(__half2*)&ku.y;
                __half2 a0 = __hmax2(__hadd2(__hsub2(q0, k0), ba1h0), hzero);
                __half2 a1 = __hmax2(__hadd2(__hsub2(q1, k1), ba1h1), hzero);
                ua.x = *(unsigned*)&a0;
                ua.y = *(unsigned*)&a1;
                float r0p = fmaf(dpx, pwx.x, fmaf(dpy, pwy.x, fmaf(dpz, pwz.x, bp1.x)));
                float r1p = fmaf(dpx, pwx.y, fmaf(dpy, pwy.y, fmaf(dpz, pwz.y, bp1.y)));
                float r2p = fmaf(dpx, pwx.z, fmaf(dpy, pwy.z, fmaf(dpz, pwz.z, bp1.z)));
                float r3p = fmaf(dpx, pwx.w, fmaf(dpy, pwy.w, fmaf(dpz, pwz.w, bp1.w)));
                up.x = pack_h2(fmaxf(r0p, 0.f), fmaxf(r1p, 0.f));
                up.y = pack_h2(fmaxf(r2p, 0.f), fmaxf(r3p, 0.f));
            } else {
                ua = make_uint2(0u, 0u);
                up = ua;
            }
            *(uint2*)(hidA16 + e * 72 + js) = ua;
            *(uint2*)(hidP16 + e * 72 + js) = up;
        }
        {
            int nv2 = vt + stride;
            if (nv2 < nvt) {
                int ib = (it ^ 1) * 32;
                if (htid < 32) {
                    int e = (nv2 << 5) + htid;
                    seB[ib + htid] = (e < E) ? src[e] : 0;
                } else if (htid < 64) {
                    int e = (nv2 << 5) + htid - 32;
                    deB[ib + htid - 32] = (e < E) ? dst[e] : -1;
                }
            }
        }
        HBAR(barId);

        float acc[2][4][4];
        #pragma unroll
        for (int s2 = 0; s2 < 2; s2++)
            #pragma unroll
            for (int nt = 0; nt < 4; nt++) {
                acc[s2][nt][0] = bias0[nt];
                acc[s2][nt][1] = bias1[nt];
                acc[s2][nt][2] = bias0[nt];
                acc[s2][nt][3] = bias1[nt];
            }
        #pragma unroll
        for (int kt = 0; kt < 4; kt++) {
            unsigned a0[4], a1[4];
            ldsm_x4(a0[0], a0[1], a0[2], a0[3], aAddr0 + kt * 32);
            ldsm_x4(a1[0], a1[1], a1[2], a1[3], aAddr1 + kt * 32);
            #pragma unroll
            for (int nt = 0; nt < 4; nt++) {
                MMA_F16(acc[0][nt], a0, bB[kt][nt].x, bB[kt][nt].y);
                MMA_F16(acc[1][nt], a1, bB[kt][nt].x, bB[kt][nt].y);
            }
        }
        {
            int rA = lane >> 2;
            int cbv = 2 * (lane & 3);
            #pragma unroll
            for (int s2 = 0; s2 < 2; s2++) {
                int rb = s2 * 16 + rA;
                #pragma unroll
                for (int nt = 0; nt < 4; nt++) {
                    int col = n0b + nt * 8 + cbv;
                    float v0, v1, v2, v3;
                    if (isA) {
                        v0 = __expf(fmaxf(acc[s2][nt][0], 0.f));
                        v1 = __expf(fmaxf(acc[s2][nt][1], 0.f));
                        v2 = __expf(fmaxf(acc[s2][nt][2], 0.f));
                        v3 = __expf(fmaxf(acc[s2][nt][3], 0.f));
                    } else {
                        v0 = fmaxf(acc[s2][nt][0], 0.f);
                        v1 = fmaxf(acc[s2][nt][1], 0.f);
                        v2 = fmaxf(acc[s2][nt][2], 0.f);
                        v3 = fmaxf(acc[s2][nt][3], 0.f);
                    }
                    *(float2*)(res + rb * 68 + col)       = make_float2(v0, v1);
                    *(float2*)(res + (rb + 8) * 68 + col) = make_float2(v2, v3);
                }
            }
        }
        HBAR(barId);
    }

    #pragma unroll
    for (int k = 0; k < 4; k++) {
        int d = dPrev[k];
        if (d >= 0) {
            int e = hgrp + 8 * k;
            float4 ex = *(const float4*)(exA + e * 68 + js);
            float4 dl = *(const float4*)(dlP + e * 68 + js);
            float4 vv = *(const float4*)(g_v + (size_t)sPrev[k] * C + js);
            float4 nv;
            nv.x = ex.x * (vv.x + dl.x);
            nv.y = ex.y * (vv.y + dl.y);
            nv.z = ex.z * (vv.z + dl.z);
            nv.w = ex.w * (vv.w + dl.w);
            RED_V4(g_num + (size_t)d * C + js, nv);
            RED_V4(g_den + (size_t)d * C + js, ex);
        }
    }
}

// ---------------- K3: out kernel — fp16 MMA + coalesced staged stores -----------
__global__ void __launch_bounds__(256)
out_kernel(const float* __restrict__ b_out, float* __restrict__ out, int n)
{
    __shared__ __half rs[64 * 72];
    __shared__ float  fb[64 * 68];
    int tid  = threadIdx.x;
    int lane = tid & 31;
    int wid  = tid >> 5;
    int base = blockIdx.x * 64;

    for (int t = tid; t < 1024; t += 256) {
        int row = t >> 4;
        int col = (t & 15) * 4;
        int node = base + row;
        float4 r = make_float4(0.f, 0.f, 0.f, 0.f);
        if (node < n) {
            float4 nu = *(const float4*)(g_num + (size_t)node * C + col);
            float4 de = *(const float4*)(g_den + (size_t)node * C + col);
            r.x = nu.x / (de.x + 1e-16f);
            r.y = nu.y / (de.y + 1e-16f);
            r.z = nu.z / (de.z + 1e-16f);
            r.w = nu.w / (de.w + 1e-16f);
        }
        uint2 u;
        u.x = pack_h2(r.x, r.y);
        u.y = pack_h2(r.z, r.w);
        *(uint2*)(rs + row * 72 + col) = u;
    }
    __syncthreads();

    int r0 = (wid & 3) * 16;
    int nh = wid >> 2;
    int n0 = nh * 32;
    int rA = lane >> 2;
    int cb = 2 * (lane & 3);

    uint32_t aR = smem_u32(rs) + (uint32_t)(((r0 + (lane & 15)) * 72 + ((lane >> 4) << 3)) * 2);

    float acc[4][4];
    #pragma unroll
    for (int nt = 0; nt < 4; nt++) {
        int col = n0 + nt * 8 + cb;
        float b0 = b_out[col], b1 = b_out[col + 1];
        acc[nt][0] = b0; acc[nt][1] = b1; acc[nt][2] = b0; acc[nt][3] = b1;
    }
    #pragma unroll
    for (int kt = 0; kt < 4; kt++) {
        unsigned a[4];
        ldsm_x4(a[0], a[1], a[2], a[3], aR + kt * 32);
        #pragma unroll
        for (int nt = 0; nt < 4; nt++) {
            uint2 b = g_hWout[(kt * 8 + nh * 4 + nt) * 32 + lane];
            MMA_F16(acc[nt], a, b.x, b.y);
        }
    }
    #pragma unroll
    for (int nt = 0; nt < 4; nt++) {
        int col = n0 + nt * 8 + cb;
        fb[(r0 + rA) * 68 + col]         = fmaxf(acc[nt][0], 0.f);
        fb[(r0 + rA) * 68 + col + 1]     = fmaxf(acc[nt][1], 0.f);
        fb[(r0 + 8 + rA) * 68 + col]     = fmaxf(acc[nt][2], 0.f);
        fb[(r0 + 8 + rA) * 68 + col + 1] = fmaxf(acc[nt][3], 0.f);
    }
    __syncthreads();

    #pragma unroll
    for (int p = 0; p < 4; p++) {
        int row = (tid >> 4) + p * 16;
        int node = base + row;
        int col = (tid & 15) * 4;
        if (node < n)
            *(float4*)(out + (size_t)node * C + col) = *(const float4*)(fb + row * 68 + col);
    }
}

// ---------------- launch --------------------------------------------------------
extern "C" void kernel_launch(void* const* d_in, const int* in_sizes, int n_in,
                              void* d_out, int out_size)
{
    const float* x      = (const float*)d_in[0];
    const float* pos    = (const float*)d_in[1];
    const int*   ei     = (const int*)  d_in[2];
    const float* W_in   = (const float*)d_in[3];
    const float* b_in   = (const float*)d_in[4];
    const float* W_out  = (const float*)d_in[5];
    const float* b_out  = (const float*)d_in[6];
    const float* W_lin  = (const float*)d_in[7];
    const float* W_src  = (const float*)d_in[8];
    const float* W_dst  = (const float*)d_in[9];
    const float* pos_w1 = (const float*)d_in[10];
    const float* pos_b1 = (const float*)d_in[11];
    const float* pos_w2 = (const float*)d_in[12];
    const float* pos_b2 = (const float*)d_in[13];
    const float* att_w1 = (const float*)d_in[14];
    const float* att_b1 = (const float*)d_in[15];
    const float* att_w2 = (const float*)d_in[16];
    const float* att_b2 = (const float*)d_in[17];

    int n = in_sizes[0] / C;
    int E = in_sizes[2] / 2;
    const int* srcArr = ei;
    const int* dstArr = ei + E;

    size_t smemNode = 53248;
    size_t smemEdge = 54272;   // 2 x 27136
    cudaFuncSetAttribute(node_kernel, cudaFuncAttributeMaxDynamicSharedMemorySize, (int)smemNode);
    cudaFuncSetAttribute(edge_kernel, cudaFuncAttributeMaxDynamicSharedMemorySize, (int)smemEdge);

    int tilesN = (n + 63) / 64;

    prep_kernel<<<1, 256>>>(att_w1, W_dst, W_src, W_in, W_lin, att_w2, pos_w2, W_out,
                            pos_b1, pos_b2);
    node_kernel<<<tilesN, 256, smemNode>>>(x, pos, b_in, att_b1, att_b2, n);
    edge_kernel<<<444, 256, smemEdge>>>(srcArr, dstArr, att_b1, pos_b1, pos_w1,
                                        att_b2, pos_b2, E);
    out_kernel<<<tilesN, 256>>>(b_out, (float*)d_out, n);
}